// round 10
// baseline (speedup 1.0000x reference)
#include <cuda_runtime.h>
#include <stdint.h>

// out[c] = FACTOR * sum_e eng[e] * scales[sp[c], sp[n]]
// R10: single persistent kernel (592 CTAs = exactly one resident wave),
// device grid barriers between phases:
//   phase0: zero tmp (.cg) + pack species nibbles + stage scales
//   phase1: smem pack table -> scatter tmp[c*16+sp[n]] += eng[e]
//   phase2: reduce out[c] = FACTOR * dot(scales[sp[c],:], tmp[c,:])
// All cross-barrier gmem traffic uses .cg (L2) ops to avoid stale L1.

#define FACTOR 0.125f  // 1/sqrt(64)
#define TPB 512
#define NBLOCKS (148 * 4)

__device__ uint32_t g_packed_species[32768];   // nibble-packed species (<=262144 nodes)
__device__ float    g_tmp[262144 * 16];        // (node, neighbor-species) accumulators
__device__ unsigned g_bar[2];                  // grid barrier counters (memset per launch)

__device__ __forceinline__ void grid_barrier(int id, int nblocks) {
    __syncthreads();
    if (threadIdx.x == 0) {
        __threadfence();
        unsigned prev = atomicAdd(&g_bar[id], 1u);
        if (prev + 1 < (unsigned)nblocks) {
            while (*((volatile unsigned*)&g_bar[id]) < (unsigned)nblocks) { }
        }
    }
    __syncthreads();
}

__global__ __launch_bounds__(TPB, 4) void fused_kernel(
    const float* __restrict__ edge_eng,     // [E]
    const float* __restrict__ scales,       // [256]
    const int*   __restrict__ ei_center,    // [E]
    const int*   __restrict__ ei_neighbor,  // [E]
    const int*   __restrict__ species,      // [N]
    float* __restrict__ out,                // [N]
    int E, int N, int nwords)
{
    extern __shared__ uint32_t smem[];
    uint32_t* s_pack  = smem;              // nwords words
    float*    s_scale = (float*)(smem + ((nwords + 3) & ~3));  // 256 floats

    int tid = threadIdx.x;
    int gtid = blockIdx.x * blockDim.x + tid;
    int gstride = gridDim.x * blockDim.x;

    // ---- Phase 0: zero tmp (.cg), pack species, stage scales ----
    if (tid < 256) s_scale[tid] = scales[tid];

    int ntmp4 = N << 2;   // N*16 floats / 4
    float4 z = make_float4(0.f, 0.f, 0.f, 0.f);
    for (int i = gtid; i < ntmp4; i += gstride)
        __stcg(&((float4*)g_tmp)[i], z);

    for (int i = gtid; i < nwords; i += gstride) {
        int base = i << 3;
        uint32_t w = 0;
        if (base + 8 <= N) {
            int4 a = *(const int4*)&species[base];
            int4 b = *(const int4*)&species[base + 4];
            w  = ((uint32_t)a.x & 0xFu)
               | (((uint32_t)a.y & 0xFu) << 4)
               | (((uint32_t)a.z & 0xFu) << 8)
               | (((uint32_t)a.w & 0xFu) << 12)
               | (((uint32_t)b.x & 0xFu) << 16)
               | (((uint32_t)b.y & 0xFu) << 20)
               | (((uint32_t)b.z & 0xFu) << 24)
               | (((uint32_t)b.w & 0xFu) << 28);
        } else {
            for (int k = 0; k < 8; k++) {
                int idx = base + k;
                if (idx < N) w |= ((uint32_t)species[idx] & 0xFu) << (k << 2);
            }
        }
        __stcg(&g_packed_species[i], w);
    }

    grid_barrier(0, gridDim.x);

    // ---- Phase 1: stage pack table in smem, then scatter ----
    for (int i = tid; i < nwords; i += blockDim.x)
        s_pack[i] = __ldcg(&g_packed_species[i]);
    __syncthreads();

    #define SPEC(idx) ((s_pack[(idx) >> 3] >> (((idx) & 7) << 2)) & 0xFu)

    int nvec = E >> 2;
    const float4* eng4 = (const float4*)edge_eng;
    const int4*   c4   = (const int4*)ei_center;
    const int4*   n4   = (const int4*)ei_neighbor;

    for (int v = gtid; v < nvec; v += gstride) {
        float4 e = __ldcs(&eng4[v]);
        int4   c = __ldcs(&c4[v]);
        int4   n = __ldcs(&n4[v]);
        atomicAdd(&g_tmp[(c.x << 4) | SPEC(n.x)], e.x);
        atomicAdd(&g_tmp[(c.y << 4) | SPEC(n.y)], e.y);
        atomicAdd(&g_tmp[(c.z << 4) | SPEC(n.z)], e.z);
        atomicAdd(&g_tmp[(c.w << 4) | SPEC(n.w)], e.w);
    }
    int base = nvec << 2;
    for (int i = base + gtid; i < E; i += gstride) {
        int cc = ei_center[i];
        int nn = ei_neighbor[i];
        atomicAdd(&g_tmp[(cc << 4) | SPEC(nn)], edge_eng[i]);
    }

    grid_barrier(1, gridDim.x);

    // ---- Phase 2: per-node reduce (center species from smem pack table) ----
    const float4* tmp4 = (const float4*)g_tmp;
    for (int i = gtid; i < N; i += gstride) {
        int sc = SPEC(i);
        const float* srow = &s_scale[sc << 4];
        float4 t0 = __ldcg(&tmp4[(i << 2) + 0]);
        float4 t1 = __ldcg(&tmp4[(i << 2) + 1]);
        float4 t2 = __ldcg(&tmp4[(i << 2) + 2]);
        float4 t3 = __ldcg(&tmp4[(i << 2) + 3]);
        float acc = 0.0f;
        acc += t0.x * srow[0]  + t0.y * srow[1]  + t0.z * srow[2]  + t0.w * srow[3];
        acc += t1.x * srow[4]  + t1.y * srow[5]  + t1.z * srow[6]  + t1.w * srow[7];
        acc += t2.x * srow[8]  + t2.y * srow[9]  + t2.z * srow[10] + t2.w * srow[11];
        acc += t3.x * srow[12] + t3.y * srow[13] + t3.z * srow[14] + t3.w * srow[15];
        out[i] = acc * FACTOR;
    }
    #undef SPEC
}

extern "C" void kernel_launch(void* const* d_in, const int* in_sizes, int n_in,
                              void* d_out, int out_size) {
    const float* edge_eng = (const float*)d_in[0];  // [E,1]
    const float* scales   = (const float*)d_in[1];  // [16,16]
    const int*   edge_idx = (const int*)d_in[2];    // [2,E]
    const int*   species  = (const int*)d_in[3];    // [N]
    float* out = (float*)d_out;

    int E = in_sizes[0];
    int N = out_size;
    int nwords = (N + 7) >> 3;

    const int* ei_center   = edge_idx;
    const int* ei_neighbor = edge_idx + E;

    // Reset grid-barrier counters (graph-capturable driver memset).
    void* bar_ptr = nullptr;
    cudaGetSymbolAddress(&bar_ptr, g_bar);
    cudaMemsetAsync(bar_ptr, 0, 2 * sizeof(unsigned), 0);

    size_t smem_bytes = (size_t)((nwords + 3) & ~3) * 4 + 256 * sizeof(float);
    cudaFuncSetAttribute(fused_kernel,
                         cudaFuncAttributeMaxDynamicSharedMemorySize,
                         (int)smem_bytes);

    fused_kernel<<<NBLOCKS, TPB, smem_bytes>>>(
        edge_eng, scales, ei_center, ei_neighbor, species, out, E, N, nwords);
}

// round 11
// speedup vs baseline: 2.2407x; 2.2407x over previous
#include <cuda_runtime.h>
#include <stdint.h>

// out[c] = FACTOR * sum_e eng[e] * scales[sp[c], sp[n]]
// pass0 (prep):   zero tmp (64B/thread) + pack species nibbles   [fused]
// pass1 (scatter): tmp[c*16 + sp[n]] += eng[e]    (1 LDS + 1 RED per edge)
// pass2 (reduce):  out[c] = FACTOR * dot(scales[sp[c],:], tmp[c,:])
// R11 = R9 revert (R10 persistent-kernel fusion regressed 2.2x) + fatter prep
// threads (4 float4 zeroes each) to cut prep from 5us toward 2us.

#define FACTOR 0.125f  // 1/sqrt(64)

__device__ uint32_t g_packed_species[32768];   // nibble-packed species (<=262144 nodes)
__device__ float    g_tmp[262144 * 16];        // (node, neighbor-species) accumulators

// Fused prep: each thread zeroes 4 float4s of tmp; first nwords threads pack nibbles.
__global__ __launch_bounds__(256) void prep_kernel(
    const int* __restrict__ species, int N, int nwords, int ntmp4)
{
    int i = blockIdx.x * blockDim.x + threadIdx.x;

    float4 z = make_float4(0.f, 0.f, 0.f, 0.f);
    float4* t4 = (float4*)g_tmp;
    int zbase = i << 2;
    #pragma unroll
    for (int k = 0; k < 4; k++) {
        int zi = zbase + k;
        if (zi < ntmp4) t4[zi] = z;
    }

    if (i < nwords) {
        int base = i << 3;
        uint32_t w = 0;
        if (base + 8 <= N) {
            int4 a = *(const int4*)&species[base];
            int4 b = *(const int4*)&species[base + 4];
            w  = ((uint32_t)a.x & 0xFu)
               | (((uint32_t)a.y & 0xFu) << 4)
               | (((uint32_t)a.z & 0xFu) << 8)
               | (((uint32_t)a.w & 0xFu) << 12)
               | (((uint32_t)b.x & 0xFu) << 16)
               | (((uint32_t)b.y & 0xFu) << 20)
               | (((uint32_t)b.z & 0xFu) << 24)
               | (((uint32_t)b.w & 0xFu) << 28);
        } else {
            for (int k = 0; k < 8; k++) {
                int idx = base + k;
                if (idx < N) w |= ((uint32_t)species[idx] & 0xFu) << (k << 2);
            }
        }
        g_packed_species[i] = w;
    }
}

// Pass 1: scatter edge energies into (center, neighbor-species) bins.
__global__ __launch_bounds__(512) void edge_scatter_kernel(
    const float* __restrict__ edge_eng,     // [E]
    const int*   __restrict__ ei_center,    // [E]
    const int*   __restrict__ ei_neighbor,  // [E]
    int E, int nwords)
{
    extern __shared__ uint32_t s_pack[];    // nwords words (~50KB)
    for (int i = threadIdx.x; i < nwords; i += blockDim.x)
        s_pack[i] = g_packed_species[i];
    __syncthreads();

    #define SPEC(idx) ((s_pack[(idx) >> 3] >> (((idx) & 7) << 2)) & 0xFu)

    int nvec = E >> 2;
    int tid = blockIdx.x * blockDim.x + threadIdx.x;
    int stride = gridDim.x * blockDim.x;

    const float4* eng4 = (const float4*)edge_eng;
    const int4*   c4   = (const int4*)ei_center;
    const int4*   n4   = (const int4*)ei_neighbor;

    for (int v = tid; v < nvec; v += stride) {
        float4 e = __ldcs(&eng4[v]);
        int4   c = __ldcs(&c4[v]);
        int4   n = __ldcs(&n4[v]);
        atomicAdd(&g_tmp[(c.x << 4) | SPEC(n.x)], e.x);
        atomicAdd(&g_tmp[(c.y << 4) | SPEC(n.y)], e.y);
        atomicAdd(&g_tmp[(c.z << 4) | SPEC(n.z)], e.z);
        atomicAdd(&g_tmp[(c.w << 4) | SPEC(n.w)], e.w);
    }

    int base = nvec << 2;
    for (int i = base + tid; i < E; i += stride) {
        int cc = ei_center[i];
        int nn = ei_neighbor[i];
        atomicAdd(&g_tmp[(cc << 4) | SPEC(nn)], edge_eng[i]);
    }
    #undef SPEC
}

// Pass 2: per-node dot product with the species-pair scale row.
__global__ __launch_bounds__(256) void node_reduce_kernel(
    const float* __restrict__ scales,   // [256]
    const int*   __restrict__ species,  // [N]
    float* __restrict__ out,            // [N]
    int N)
{
    __shared__ float s_scale[256];
    if (threadIdx.x < 256) s_scale[threadIdx.x] = scales[threadIdx.x];
    __syncthreads();

    int i = blockIdx.x * blockDim.x + threadIdx.x;
    if (i >= N) return;

    int sc = species[i] & 0xF;
    const float* srow = &s_scale[sc << 4];
    const float4* tp = (const float4*)&g_tmp[i << 4];

    float4 t0 = tp[0], t1 = tp[1], t2 = tp[2], t3 = tp[3];
    float acc = 0.0f;
    acc += t0.x * srow[0]  + t0.y * srow[1]  + t0.z * srow[2]  + t0.w * srow[3];
    acc += t1.x * srow[4]  + t1.y * srow[5]  + t1.z * srow[6]  + t1.w * srow[7];
    acc += t2.x * srow[8]  + t2.y * srow[9]  + t2.z * srow[10] + t2.w * srow[11];
    acc += t3.x * srow[12] + t3.y * srow[13] + t3.z * srow[14] + t3.w * srow[15];
    out[i] = acc * FACTOR;
}

extern "C" void kernel_launch(void* const* d_in, const int* in_sizes, int n_in,
                              void* d_out, int out_size) {
    const float* edge_eng = (const float*)d_in[0];  // [E,1]
    const float* scales   = (const float*)d_in[1];  // [16,16]
    const int*   edge_idx = (const int*)d_in[2];    // [2,E]
    const int*   species  = (const int*)d_in[3];    // [N]
    float* out = (float*)d_out;

    int E = in_sizes[0];
    int N = out_size;
    int nwords = (N + 7) >> 3;
    int ntmp4 = N << 2;   // N*16 floats / 4 per float4

    const int* ei_center   = edge_idx;
    const int* ei_neighbor = edge_idx + E;

    // prep: each thread zeroes 4 float4s; packing needs nwords threads.
    int zthreads = (ntmp4 + 3) >> 2;
    int prep_n = (zthreads > nwords ? zthreads : nwords);
    prep_kernel<<<(prep_n + 255) / 256, 256>>>(species, N, nwords, ntmp4);

    size_t smem_bytes = (size_t)nwords * sizeof(uint32_t);
    cudaFuncSetAttribute(edge_scatter_kernel,
                         cudaFuncAttributeMaxDynamicSharedMemorySize,
                         (int)smem_bytes);

    int threads = 512;
    int blocks = 148 * 4;   // one wave; pack-table staging cost scales with grid
    int nvec = E >> 2;
    int need = (nvec + threads - 1) / threads;
    if (blocks > need) blocks = need > 0 ? need : 1;
    edge_scatter_kernel<<<blocks, threads, smem_bytes>>>(
        edge_eng, ei_center, ei_neighbor, E, nwords);

    node_reduce_kernel<<<(N + 255) / 256, 256>>>(scales, species, out, N);
}

// round 12
// speedup vs baseline: 2.2930x; 1.0233x over previous
#include <cuda_runtime.h>
#include <stdint.h>

// out[c] = FACTOR * sum_e eng[e] * scales[sp[c], sp[n]]
// R12: "self-cleaning" tmp — module-load zero-init + reduce pass re-zeroes the
// bins it reads, so NO per-launch zero-fill pass is needed (prep was 5-6us of
// pure overhead). Pipeline:
//   pack:    species -> nibble table (12.5K threads, tiny)
//   scatter: tmp[c*16 + sp[n]] += eng[e]   (1 LDS + 1 RED per edge; at the
//            scattered-RED L1tex-wavefront floor per R3-R11 analysis)
//   reduce:  out[c] = FACTOR * dot(scales[sp[c],:], tmp[c,:]); tmp[c,:] = 0

#define FACTOR 0.125f  // 1/sqrt(64)

__device__ uint32_t g_packed_species[32768];   // nibble-packed species (<=262144 nodes)
__device__ float    g_tmp[262144 * 16];        // zero at module load; reduce keeps it zero

__global__ __launch_bounds__(256) void pack_kernel(
    const int* __restrict__ species, int N, int nwords)
{
    int i = blockIdx.x * blockDim.x + threadIdx.x;
    if (i >= nwords) return;
    int base = i << 3;
    uint32_t w = 0;
    if (base + 8 <= N) {
        int4 a = *(const int4*)&species[base];
        int4 b = *(const int4*)&species[base + 4];
        w  = ((uint32_t)a.x & 0xFu)
           | (((uint32_t)a.y & 0xFu) << 4)
           | (((uint32_t)a.z & 0xFu) << 8)
           | (((uint32_t)a.w & 0xFu) << 12)
           | (((uint32_t)b.x & 0xFu) << 16)
           | (((uint32_t)b.y & 0xFu) << 20)
           | (((uint32_t)b.z & 0xFu) << 24)
           | (((uint32_t)b.w & 0xFu) << 28);
    } else {
        for (int k = 0; k < 8; k++) {
            int idx = base + k;
            if (idx < N) w |= ((uint32_t)species[idx] & 0xFu) << (k << 2);
        }
    }
    g_packed_species[i] = w;
}

__global__ __launch_bounds__(512) void edge_scatter_kernel(
    const float* __restrict__ edge_eng,     // [E]
    const int*   __restrict__ ei_center,    // [E]
    const int*   __restrict__ ei_neighbor,  // [E]
    int E, int nwords)
{
    extern __shared__ uint32_t s_pack[];    // nwords words (~50KB)
    for (int i = threadIdx.x; i < nwords; i += blockDim.x)
        s_pack[i] = g_packed_species[i];
    __syncthreads();

    #define SPEC(idx) ((s_pack[(idx) >> 3] >> (((idx) & 7) << 2)) & 0xFu)

    int nvec = E >> 2;
    int tid = blockIdx.x * blockDim.x + threadIdx.x;
    int stride = gridDim.x * blockDim.x;

    const float4* eng4 = (const float4*)edge_eng;
    const int4*   c4   = (const int4*)ei_center;
    const int4*   n4   = (const int4*)ei_neighbor;

    for (int v = tid; v < nvec; v += stride) {
        float4 e = __ldcs(&eng4[v]);
        int4   c = __ldcs(&c4[v]);
        int4   n = __ldcs(&n4[v]);
        atomicAdd(&g_tmp[(c.x << 4) | SPEC(n.x)], e.x);
        atomicAdd(&g_tmp[(c.y << 4) | SPEC(n.y)], e.y);
        atomicAdd(&g_tmp[(c.z << 4) | SPEC(n.z)], e.z);
        atomicAdd(&g_tmp[(c.w << 4) | SPEC(n.w)], e.w);
    }

    int base = nvec << 2;
    for (int i = base + tid; i < E; i += stride) {
        int cc = ei_center[i];
        int nn = ei_neighbor[i];
        atomicAdd(&g_tmp[(cc << 4) | SPEC(nn)], edge_eng[i]);
    }
    #undef SPEC
}

// Reduce + reset: read the 16 bins for node i, dot with the species row,
// then zero the bins so the next launch starts clean.
__global__ __launch_bounds__(256) void node_reduce_kernel(
    const float* __restrict__ scales,   // [256]
    const int*   __restrict__ species,  // [N]
    float* __restrict__ out,            // [N]
    int N)
{
    __shared__ float s_scale[256];
    if (threadIdx.x < 256) s_scale[threadIdx.x] = scales[threadIdx.x];
    __syncthreads();

    int i = blockIdx.x * blockDim.x + threadIdx.x;
    if (i >= N) return;

    int sc = species[i] & 0xF;
    const float* srow = &s_scale[sc << 4];
    float4* tp = (float4*)&g_tmp[i << 4];

    float4 t0 = tp[0], t1 = tp[1], t2 = tp[2], t3 = tp[3];
    float acc = 0.0f;
    acc += t0.x * srow[0]  + t0.y * srow[1]  + t0.z * srow[2]  + t0.w * srow[3];
    acc += t1.x * srow[4]  + t1.y * srow[5]  + t1.z * srow[6]  + t1.w * srow[7];
    acc += t2.x * srow[8]  + t2.y * srow[9]  + t2.z * srow[10] + t2.w * srow[11];
    acc += t3.x * srow[12] + t3.y * srow[13] + t3.z * srow[14] + t3.w * srow[15];
    out[i] = acc * FACTOR;

    // Reset bins for the next launch (lines are hot in L2 right now).
    float4 z = make_float4(0.f, 0.f, 0.f, 0.f);
    tp[0] = z; tp[1] = z; tp[2] = z; tp[3] = z;
}

extern "C" void kernel_launch(void* const* d_in, const int* in_sizes, int n_in,
                              void* d_out, int out_size) {
    const float* edge_eng = (const float*)d_in[0];  // [E,1]
    const float* scales   = (const float*)d_in[1];  // [16,16]
    const int*   edge_idx = (const int*)d_in[2];    // [2,E]
    const int*   species  = (const int*)d_in[3];    // [N]
    float* out = (float*)d_out;

    int E = in_sizes[0];
    int N = out_size;
    int nwords = (N + 7) >> 3;

    const int* ei_center   = edge_idx;
    const int* ei_neighbor = edge_idx + E;

    pack_kernel<<<(nwords + 255) / 256, 256>>>(species, N, nwords);

    size_t smem_bytes = (size_t)nwords * sizeof(uint32_t);
    cudaFuncSetAttribute(edge_scatter_kernel,
                         cudaFuncAttributeMaxDynamicSharedMemorySize,
                         (int)smem_bytes);

    int threads = 512;
    int blocks = 148 * 4;   // one wave
    int nvec = E >> 2;
    int need = (nvec + threads - 1) / threads;
    if (blocks > need) blocks = need > 0 ? need : 1;
    edge_scatter_kernel<<<blocks, threads, smem_bytes>>>(
        edge_eng, ei_center, ei_neighbor, E, nwords);

    node_reduce_kernel<<<(N + 255) / 256, 256>>>(scales, species, out, N);
}